// round 17
// baseline (speedup 1.0000x reference)
#include <cuda_runtime.h>
#include <cuda_fp16.h>
#include <math.h>
#include <stdint.h>

// ---------------------------------------------------------------------------
// GCN node classifier.
//   CSR by destination (+implicit self loop), dinv = rsqrt(deg+1).
//   layer1: H = X @ W1 (RAW, bf16);  Y[v] = relu(dinv[v]*(S dinv[u] H[u] +
//           dinv[v] H[v]) + b1)   <- source scaling moved into agg so gemm1
//           has NO CSR dependency and forks at t=0 beside the whole build.
//   layer2: G2 = dinv*(Y @ W2) (bf16);  Y[v] = relu(dinv[v]*(S G2[u]+G2[v])+b2)
//   head:   OUT = Y @ Wl + bl  [FP32]
// Split-pipelining (R16) retained: gemm2a||agg1b, head_a||agg2b.
// ---------------------------------------------------------------------------

#define N_NODES 40000
#define C_FEAT  128
#define N_EDGES 640000
#define SPLIT   20032              // 313 * 64
#define SA_BLK  313                // rows [0, SPLIT)
#define SB_BLK  312                // rows [SPLIT, N_NODES)

__device__ uint32_t d_g [(size_t)N_NODES * C_FEAT / 2];  // layer-1 bf16x2 (raw H)
__device__ uint32_t d_g2[(size_t)N_NODES * C_FEAT / 2];  // layer-2 bf16x2
__device__ float    d_y[(size_t)N_NODES * C_FEAT];       // fp32
__device__ int      d_cnt[N_NODES];    // zero-init; scan re-zeroes after use
__device__ int      d_off[N_NODES + 1];
__device__ int      d_cursor[N_NODES];
__device__ int      d_adj[N_EDGES];
__device__ float    d_dinv[N_NODES];

// ---------------------------------------------------------------------------
__global__ void hist_kernel(const int* __restrict__ ei, int E) {
    int i = blockIdx.x * blockDim.x + threadIdx.x;
    if (i * 4 < E) {
        int4 v = *(const int4*)&ei[E + i * 4];
        atomicAdd(&d_cnt[v.x], 1);
        atomicAdd(&d_cnt[v.y], 1);
        atomicAdd(&d_cnt[v.z], 1);
        atomicAdd(&d_cnt[v.w], 1);
    }
}

// Single 1024-thread block; 40 coalesced tiles, register prefetch, reg carry.
__global__ void scan_kernel() {
    __shared__ int wred[33];
    const int NT = (N_NODES + 1023) / 1024;   // 40 tiles
    int tid = threadIdx.x, lane = tid & 31, wid = tid >> 5;
    int carry = 0;

    int c = d_cnt[tid];
    for (int t = 0; t < NT; t++) {
        int inext = (t + 1) * 1024 + tid;
        int cn = 0;
        if (t + 1 < NT && inext < N_NODES) cn = d_cnt[inext];   // prefetch

        int v = c;
#pragma unroll
        for (int d = 1; d < 32; d <<= 1) {
            int u = __shfl_up_sync(0xffffffffu, v, d);
            if (lane >= d) v += u;
        }
        __syncthreads();
        if (lane == 31) wred[wid] = v;
        __syncthreads();
        if (wid == 0) {
            int wv = wred[lane];
            int iv = wv;
#pragma unroll
            for (int d = 1; d < 32; d <<= 1) {
                int u = __shfl_up_sync(0xffffffffu, iv, d);
                if (lane >= d) iv += u;
            }
            wred[lane] = iv - wv;
            if (lane == 31) wred[32] = iv;
        }
        __syncthreads();
        int i = t * 1024 + tid;
        int pos = carry + wred[wid] + (v - c);
        if (i < N_NODES) {
            d_off[i] = pos;
            d_cursor[i] = pos;
            d_dinv[i] = rsqrtf((float)(c + 1));
            d_cnt[i] = 0;                 // restore invariant for next replay
        }
        carry += wred[32];
        c = cn;
    }
    if (tid == 0) d_off[N_NODES] = carry;
}

__global__ void scatter_kernel(const int* __restrict__ ei, int E) {
    int i = blockIdx.x * blockDim.x + threadIdx.x;
    if (i * 4 < E) {
        int4 r = *(const int4*)&ei[i * 4];       // sources
        int4 c = *(const int4*)&ei[E + i * 4];   // targets
        d_adj[atomicAdd(&d_cursor[c.x], 1)] = r.x;
        d_adj[atomicAdd(&d_cursor[c.y], 1)] = r.y;
        d_adj[atomicAdd(&d_cursor[c.z], 1)] = r.z;
        d_adj[atomicAdd(&d_cursor[c.w], 1)] = r.w;
    }
}

// ---------------------------------------------------------------------------
// bf16 helpers: pack (cvt), unpack + fma accumulate (ALU unpack + FFMA).
// ---------------------------------------------------------------------------
__device__ __forceinline__ uint32_t pack_bf2(float lo, float hi) {
    uint32_t r;
    asm("cvt.rn.bf16x2.f32 %0, %1, %2;" : "=r"(r) : "f"(hi), "f"(lo));
    return r;
}

__device__ __forceinline__ void accbs(float4& a, uint2 v, float s) {
    a.x = fmaf(s, __uint_as_float(v.x << 16), a.x);
    a.y = fmaf(s, __uint_as_float(v.x & 0xFFFF0000u), a.y);
    a.z = fmaf(s, __uint_as_float(v.y << 16), a.z);
    a.w = fmaf(s, __uint_as_float(v.y & 0xFFFF0000u), a.w);
}

// ---------------------------------------------------------------------------
// tf32 tensor-core GEMM, cp.async 2-stage pipeline.
// C = A[rows,128] @ B[128,BN].  CTA: 64 x BN, 8 warps (2x4), warp 32 x BN/4.
// a_sel: 0=Aext 1=d_y.  c_sel: 0=fp32 Cext, 1=bf16 d_g, 2=bf16 d_g2.
// ---------------------------------------------------------------------------
__device__ __forceinline__ uint32_t f2tf(float f) {
    uint32_t r;
    asm("cvt.rna.tf32.f32 %0, %1;" : "=r"(r) : "f"(f));
    return r;
}

__device__ __forceinline__ void cp16(uint32_t saddr, const void* gptr) {
    asm volatile("cp.async.ca.shared.global [%0], [%1], 16;\n"
                 :: "r"(saddr), "l"(gptr));
}

template <int BN>
__global__ void __launch_bounds__(256, 3)
gemm_tf32_kernel(const float* __restrict__ Aext,
                 const float* __restrict__ B,
                 const float* __restrict__ bias,
                 float* __restrict__ Cext,
                 int a_sel, int c_sel, int use_rowscale, int row_base) {
    constexpr int BM = 64, KC = 16, NKC = C_FEAT / KC;   // 8 chunks
    constexpr int AP = 20;
    constexpr int NP = BN + 8;
    constexpr int WN = BN / 4;
    constexpr int MF = 2;
    constexpr int NF = WN / 8;
    constexpr int BV = KC * BN / 4;

    __shared__ float As[2][BM * AP];
    __shared__ float Bs[2][KC * NP];

    const float* A = (a_sel == 0) ? Aext : (const float*)d_y;

    int tid = threadIdx.x;
    int lane = tid & 31;
    int wid = tid >> 5;
    int warp_m = wid & 1;
    int warp_n = wid >> 1;
    int qid = lane >> 2;
    int qt = lane & 3;
    int row0 = row_base + blockIdx.x * BM;

    uint32_t a_smem[2], b_smem[2];
#pragma unroll
    for (int s = 0; s < 2; s++) {
        a_smem[s] = (uint32_t)__cvta_generic_to_shared(&As[s][0]);
        b_smem[s] = (uint32_t)__cvta_generic_to_shared(&Bs[s][0]);
    }

    auto load_chunk = [&](int kc, int st) {
        int k0 = kc * KC;
        {
            int r = tid >> 2, vv = tid & 3;
            int gr = row0 + r; if (gr >= N_NODES) gr = N_NODES - 1;
            cp16(a_smem[st] + (r * AP + vv * 4) * 4,
                 &A[(size_t)gr * C_FEAT + k0 + vv * 4]);
        }
#pragma unroll
        for (int i = 0; i < BV / 256; i++) {
            int idx = tid + i * 256;
            int r = idx / (BN / 4), vv = idx % (BN / 4);
            cp16(b_smem[st] + (r * NP + vv * 4) * 4,
                 &B[(size_t)(k0 + r) * BN + vv * 4]);
        }
        asm volatile("cp.async.commit_group;" ::: "memory");
    };

    float acc[MF][NF][4];
#pragma unroll
    for (int i = 0; i < MF; i++)
#pragma unroll
        for (int j = 0; j < NF; j++)
#pragma unroll
            for (int k = 0; k < 4; k++) acc[i][j][k] = 0.f;

    load_chunk(0, 0);

    for (int kc = 0; kc < NKC; kc++) {
        int st = kc & 1;
        if (kc + 1 < NKC) {
            load_chunk(kc + 1, st ^ 1);
            asm volatile("cp.async.wait_group 1;" ::: "memory");
        } else {
            asm volatile("cp.async.wait_group 0;" ::: "memory");
        }
        __syncthreads();

        const float* __restrict__ Asb = As[st];
        const float* __restrict__ Bsb = Bs[st];
#pragma unroll
        for (int k8 = 0; k8 < KC / 8; k8++) {
            int kb = k8 * 8;
            uint32_t af[MF][4];
#pragma unroll
            for (int im = 0; im < MF; im++) {
                int m0 = warp_m * 32 + im * 16 + qid;
                af[im][0] = f2tf(Asb[m0 * AP + kb + qt]);
                af[im][1] = f2tf(Asb[(m0 + 8) * AP + kb + qt]);
                af[im][2] = f2tf(Asb[m0 * AP + kb + qt + 4]);
                af[im][3] = f2tf(Asb[(m0 + 8) * AP + kb + qt + 4]);
            }
            uint32_t bf[NF][2];
#pragma unroll
            for (int jn = 0; jn < NF; jn++) {
                int n0 = warp_n * WN + jn * 8 + qid;
                bf[jn][0] = f2tf(Bsb[(kb + qt) * NP + n0]);
                bf[jn][1] = f2tf(Bsb[(kb + qt + 4) * NP + n0]);
            }
#pragma unroll
            for (int im = 0; im < MF; im++)
#pragma unroll
                for (int jn = 0; jn < NF; jn++) {
                    asm volatile(
                        "mma.sync.aligned.m16n8k8.row.col.f32.tf32.tf32.f32 "
                        "{%0,%1,%2,%3}, {%4,%5,%6,%7}, {%8,%9}, {%0,%1,%2,%3};\n"
                        : "+f"(acc[im][jn][0]), "+f"(acc[im][jn][1]),
                          "+f"(acc[im][jn][2]), "+f"(acc[im][jn][3])
                        : "r"(af[im][0]), "r"(af[im][1]), "r"(af[im][2]), "r"(af[im][3]),
                          "r"(bf[jn][0]), "r"(bf[jn][1]));
                }
        }
        __syncthreads();
    }

    uint32_t* Cb = (c_sel == 1) ? d_g : d_g2;
#pragma unroll
    for (int im = 0; im < MF; im++) {
        int ra = row0 + warp_m * 32 + im * 16 + qid;
        int rb = ra + 8;
        float sa = 1.f, sb = 1.f;
        if (use_rowscale) {
            if (ra < N_NODES) sa = d_dinv[ra];
            if (rb < N_NODES) sb = d_dinv[rb];
        }
#pragma unroll
        for (int jn = 0; jn < NF; jn++) {
            int col = warp_n * WN + jn * 8 + qt * 2;
            float bx = 0.f, by = 0.f;
            if (bias) { bx = bias[col]; by = bias[col + 1]; }
            float oax = fmaf(acc[im][jn][0], sa, bx), oay = fmaf(acc[im][jn][1], sa, by);
            float obx = fmaf(acc[im][jn][2], sb, bx), oby = fmaf(acc[im][jn][3], sb, by);
            if (c_sel) {
                if (ra < N_NODES)
                    Cb[(size_t)ra * (C_FEAT / 2) + (col >> 1)] = pack_bf2(oax, oay);
                if (rb < N_NODES)
                    Cb[(size_t)rb * (C_FEAT / 2) + (col >> 1)] = pack_bf2(obx, oby);
            } else {
                if (ra < N_NODES)
                    *(float2*)&Cext[(size_t)ra * BN + col] = make_float2(oax, oay);
                if (rb < N_NODES)
                    *(float2*)&Cext[(size_t)rb * BN + col] = make_float2(obx, oby);
            }
        }
    }
}

// ---------------------------------------------------------------------------
// Aggregation: one warp per node, bf16x2 gathers, fp32 accumulate.
// src_scale=1 (layer 1): g holds RAW H; weight each source by d_dinv[u]
// (broadcast 4B load) and self by d_dinv[v].  src_scale=0 (layer 2): g already
// dinv-scaled; multiplier 1.0 (fmaf(1,x,a) == x+a exactly).
// ---------------------------------------------------------------------------
__global__ void agg_kernel(const float* __restrict__ bias, int g_sel,
                           int src_scale, int node_base, int node_end) {
    int gw = node_base + ((blockIdx.x * blockDim.x + threadIdx.x) >> 5);
    if (gw >= node_end) return;
    int lane = threadIdx.x & 31;
    int cw = lane << 1;
    const uint32_t* __restrict__ g = (g_sel == 1) ? d_g : d_g2;

    float dvv = d_dinv[gw];
    float4 a0 = make_float4(0.f, 0.f, 0.f, 0.f);
    float4 a1 = a0, a2 = a0, a3 = a0;
    // self loop
    accbs(a0, *(const uint2*)&g[(size_t)gw * (C_FEAT / 2) + cw],
          src_scale ? dvv : 1.0f);

    int s = d_off[gw], e = d_off[gw + 1];
    for (int base = s; base < e; base += 32) {
        int m = e - base; if (m > 32) m = 32;
        int myu = (lane < m) ? d_adj[base + lane] : 0;
        int j = 0;
        for (; j + 4 <= m; j += 4) {
            int u0 = __shfl_sync(0xffffffffu, myu, j);
            int u1 = __shfl_sync(0xffffffffu, myu, j + 1);
            int u2 = __shfl_sync(0xffffffffu, myu, j + 2);
            int u3 = __shfl_sync(0xffffffffu, myu, j + 3);
            float s0 = src_scale ? d_dinv[u0] : 1.0f;
            float s1 = src_scale ? d_dinv[u1] : 1.0f;
            float s2 = src_scale ? d_dinv[u2] : 1.0f;
            float s3 = src_scale ? d_dinv[u3] : 1.0f;
            uint2 t0 = *(const uint2*)&g[(size_t)u0 * (C_FEAT / 2) + cw];
            uint2 t1 = *(const uint2*)&g[(size_t)u1 * (C_FEAT / 2) + cw];
            uint2 t2 = *(const uint2*)&g[(size_t)u2 * (C_FEAT / 2) + cw];
            uint2 t3 = *(const uint2*)&g[(size_t)u3 * (C_FEAT / 2) + cw];
            accbs(a0, t0, s0); accbs(a1, t1, s1);
            accbs(a2, t2, s2); accbs(a3, t3, s3);
        }
        for (; j < m; j++) {
            int u = __shfl_sync(0xffffffffu, myu, j);
            float su = src_scale ? d_dinv[u] : 1.0f;
            accbs(a0, *(const uint2*)&g[(size_t)u * (C_FEAT / 2) + cw], su);
        }
    }
    float4 acc = make_float4(a0.x + a1.x + a2.x + a3.x,
                             a0.y + a1.y + a2.y + a3.y,
                             a0.z + a1.z + a2.z + a3.z,
                             a0.w + a1.w + a2.w + a3.w);
    int c = lane << 2;
    float4 bb = *(const float4*)&bias[c];
    float4 o;
    o.x = fmaxf(fmaf(acc.x, dvv, bb.x), 0.f);
    o.y = fmaxf(fmaf(acc.y, dvv, bb.y), 0.f);
    o.z = fmaxf(fmaf(acc.z, dvv, bb.z), 0.f);
    o.w = fmaxf(fmaf(acc.w, dvv, bb.w), 0.f);
    *(float4*)&d_y[(size_t)gw * C_FEAT + c] = o;
}

// ---------------------------------------------------------------------------
extern "C" void kernel_launch(void* const* d_in, const int* in_sizes, int n_in,
                              void* d_out, int out_size) {
    const float* x  = (const float*)d_in[0];
    const int*   ei = (const int*)d_in[1];     // int32
    const float* W1 = (const float*)d_in[2];
    const float* b1 = (const float*)d_in[3];
    const float* W2 = (const float*)d_in[4];
    const float* b2 = (const float*)d_in[5];
    const float* Wl = (const float*)d_in[6];
    const float* bl = (const float*)d_in[7];
    float* out = (float*)d_out;

    int E = in_sizes[1] / 2;   // 640000

    static cudaStream_t s2 = []() {
        cudaStream_t s; cudaStreamCreateWithFlags(&s, cudaStreamNonBlocking); return s;
    }();
    static cudaEvent_t ev[6] = {};
    if (!ev[0]) {
        for (int i = 0; i < 6; i++)
            cudaEventCreateWithFlags(&ev[i], cudaEventDisableTiming);
    }

    const int AGG_A = (SPLIT * 32) / 256;
    const int AGG_B = ((N_NODES - SPLIT) * 32 + 255) / 256;

    // Fork 1 at t=0: gemm1 (x @ W1 -> RAW d_g; no dinv needed!) runs beside
    // the ENTIRE CSR build.
    cudaEventRecord(ev[0], 0);
    cudaStreamWaitEvent(s2, ev[0], 0);
    gemm_tf32_kernel<128><<<SA_BLK + SB_BLK, 256, 0, s2>>>(x, W1, nullptr, nullptr, 0, 1, 0, 0);
    cudaEventRecord(ev[1], s2);

    hist_kernel<<<(E / 4 + 255) / 256, 256>>>(ei, E);
    scan_kernel<<<1, 1024>>>();
    scatter_kernel<<<(E / 4 + 255) / 256, 256>>>(ei, E);
    cudaStreamWaitEvent(0, ev[1], 0);

    // agg1a (nodes [0,SPLIT), src-scaled) -> y[0:S]
    agg_kernel<<<AGG_A, 256>>>(b1, 1, 1, 0, SPLIT);

    // Fork 2: gemm2a (rows [0,SPLIT), y -> d_g2, dinv-scaled) || agg1b.
    cudaEventRecord(ev[2], 0);
    cudaStreamWaitEvent(s2, ev[2], 0);
    gemm_tf32_kernel<128><<<SA_BLK, 256, 0, s2>>>(nullptr, W2, nullptr, nullptr, 1, 2, 1, 0);
    cudaEventRecord(ev[3], s2);
    agg_kernel<<<AGG_B, 256>>>(b1, 1, 1, SPLIT, N_NODES);
    cudaStreamWaitEvent(0, ev[3], 0);

    // gemm2b (rows [SPLIT,N)).
    gemm_tf32_kernel<128><<<SB_BLK, 256>>>(nullptr, W2, nullptr, nullptr, 1, 2, 1, SPLIT);

    // agg2a (nodes [0,SPLIT), no src scaling) -> y[0:S]
    agg_kernel<<<AGG_A, 256>>>(b2, 2, 0, 0, SPLIT);

    // Fork 3: head_a || agg2b.
    cudaEventRecord(ev[4], 0);
    cudaStreamWaitEvent(s2, ev[4], 0);
    gemm_tf32_kernel<64><<<SA_BLK, 256, 0, s2>>>(nullptr, Wl, bl, out, 1, 0, 0, 0);
    cudaEventRecord(ev[5], s2);
    agg_kernel<<<AGG_B, 256>>>(b2, 2, 0, SPLIT, N_NODES);
    cudaStreamWaitEvent(0, ev[5], 0);

    // head_b (rows [SPLIT,N)).
    gemm_tf32_kernel<64><<<SB_BLK, 256>>>(nullptr, Wl, bl, out, 1, 0, 0, SPLIT);
}